// round 15
// baseline (speedup 1.0000x reference)
#include <cuda_runtime.h>

#define NPTS   16384
#define NB     1024
#define YB     64
#define XMIN   (-5.0f)
#define INVW   ((float)NB / 10.0f)
#define SLAB   512
#define NSLAB  (NPTS / SLAB)              // 32
#define CELL   128
#define NCELL  (NPTS / CELL)              // 128
#define NQW    (NPTS / 32)                // 512 warps per set
#define PREPT  1024
#define OFFB   1024                       // k_off blocks (8 warps each)
#define MAXWORK (2 * NQW * NCELL)

typedef unsigned int u32;

// set 0 = predict, set 1 = target; pass p: queries = set p, refs = set 1-p
__device__ float4 g_pts[2][NPTS];         // x-slab then y-sorted (x,y,z, 0.5|p|^2)
__device__ u32    g_minbits[2][NPTS];     // flipped min-e
__device__ float4 g_ext[2][NCELL];        // per ref-cell box (xmin,xmax,ymin,ymax)
__device__ float4 g_wext[2][NQW];         // per warp box
__device__ int    g_nwork;
__device__ int    g_done;
__device__ int    g_work[MAXWORK];        // p<<16 | qw<<7 | rc

__device__ __forceinline__ int bin_of(float x) {
    int b = (int)((x - XMIN) * INVW);
    return min(max(b, 0), NB - 1);
}
__device__ __forceinline__ u32 fflip(float f) {
    u32 u = __float_as_uint(f);
    return (u & 0x80000000u) ? ~u : (u | 0x80000000u);
}
__device__ __forceinline__ float funflip(u32 u) {
    u = (u & 0x80000000u) ? (u ^ 0x80000000u) : ~u;
    return __uint_as_float(u);
}
__device__ __forceinline__ float warpmax(float v) {
#pragma unroll
    for (int o = 16; o > 0; o >>= 1)
        v = fmaxf(v, __shfl_xor_sync(0xFFFFFFFFu, v, o));
    return v;
}
// dense eval of 32 refs (shared), returns running min-e
__device__ __forceinline__ float eval32(const float4* r, float nx, float ny,
                                        float nz, float m) {
    float m0 = m, m1 = __int_as_float(0x7f800000);
#pragma unroll
    for (int j = 0; j < 32; j += 2) {
        float4 t0 = r[j], t1 = r[j + 1];
        float e;
        e = __fmaf_rn(nx, t0.x, t0.w); e = __fmaf_rn(ny, t0.y, e); e = __fmaf_rn(nz, t0.z, e);
        m0 = fminf(m0, e);
        e = __fmaf_rn(nx, t1.x, t1.w); e = __fmaf_rn(ny, t1.y, e); e = __fmaf_rn(nz, t1.z, e);
        m1 = fminf(m1, e);
    }
    return fminf(m0, m1);
}

// ---------- K1: x-bin sort, warp-shuffle scan ----------
__global__ void __launch_bounds__(PREPT)
k_prep(const float* __restrict__ pr, const float* __restrict__ tg) {
    __shared__ int sh[NB];
    __shared__ int wsum[32];
    const int s = blockIdx.x;
    const int tid = threadIdx.x;
    const int lane = tid & 31, w = tid >> 5;
    const float* __restrict__ src = s ? tg : pr;

    if (s == 0 && tid == 0) { g_nwork = 0; g_done = 0; }

    sh[tid] = 0;
    __syncthreads();
#pragma unroll
    for (int k = 0; k < NPTS / PREPT; k++) {
        int i = tid + k * PREPT;
        atomicAdd(&sh[bin_of(src[3 * i])], 1);
    }
    __syncthreads();

    // warp-shuffle inclusive scan (2 barriers total)
    int c = sh[tid];
    int v = c;
#pragma unroll
    for (int o = 1; o < 32; o <<= 1) {
        int n = __shfl_up_sync(0xFFFFFFFFu, v, o);
        if (lane >= o) v += n;
    }
    if (lane == 31) wsum[w] = v;
    __syncthreads();
    if (w == 0) {
        int t = wsum[lane];
#pragma unroll
        for (int o = 1; o < 32; o <<= 1) {
            int n = __shfl_up_sync(0xFFFFFFFFu, t, o);
            if (lane >= o) t += n;
        }
        wsum[lane] = t;
    }
    __syncthreads();
    int base = (w > 0) ? wsum[w - 1] : 0;
    sh[tid] = base + v - c;                 // exclusive offset = scatter cursor
    __syncthreads();

#pragma unroll
    for (int k = 0; k < NPTS / PREPT; k++) {
        int i = tid + k * PREPT;
        float x = src[3 * i], y = src[3 * i + 1], z = src[3 * i + 2];
        int pos = atomicAdd(&sh[bin_of(x)], 1);
        g_pts[s][pos] = make_float4(x, y, z, 0.5f * (x * x + y * y + z * z));
    }
}

// ---------- K2: y-sort each slab + per-warp boxes + per-cell boxes ----------
__global__ void __launch_bounds__(SLAB)
k_ysort() {
    __shared__ float4 buf[SLAB];
    __shared__ int hist[YB];
    __shared__ int cur[YB];
    __shared__ float wred[16][4];
    const int slab = blockIdx.x, set = blockIdx.y, tid = threadIdx.x;
    const int base = slab * SLAB;
    const int lane = tid & 31, wid = tid >> 5;

    float4 pt = g_pts[set][base + tid];
    if (tid < YB) hist[tid] = 0;
    __syncthreads();
    int yb = min(max((int)((pt.y - XMIN) * ((float)YB / 10.0f)), 0), YB - 1);
    atomicAdd(&hist[yb], 1);
    __syncthreads();
    if (tid == 0) {
        int acc = 0;
        for (int b = 0; b < YB; b++) { int v = hist[b]; cur[b] = acc; acc += v; }
    }
    __syncthreads();
    int pos = atomicAdd(&cur[yb], 1);
    buf[pos] = pt;
    __syncthreads();
    float4 sp = buf[tid];
    g_pts[set][base + tid] = sp;

    float xn = sp.x, xm = sp.x, yn = sp.y, ym = sp.y;
#pragma unroll
    for (int o = 16; o > 0; o >>= 1) {
        xn = fminf(xn, __shfl_xor_sync(0xFFFFFFFFu, xn, o));
        xm = fmaxf(xm, __shfl_xor_sync(0xFFFFFFFFu, xm, o));
        yn = fminf(yn, __shfl_xor_sync(0xFFFFFFFFu, yn, o));
        ym = fmaxf(ym, __shfl_xor_sync(0xFFFFFFFFu, ym, o));
    }
    if (lane == 0) {
        g_wext[set][slab * 16 + wid] = make_float4(xn, xm, yn, ym);
        wred[wid][0] = xn; wred[wid][1] = xm; wred[wid][2] = yn; wred[wid][3] = ym;
    }
    __syncthreads();
    if (tid < 4) {
        float cxn = wred[4 * tid][0], cxm = wred[4 * tid][1];
        float cyn = wred[4 * tid][2], cym = wred[4 * tid][3];
#pragma unroll
        for (int w = 1; w < 4; w++) {
            cxn = fminf(cxn, wred[4 * tid + w][0]);
            cxm = fmaxf(cxm, wred[4 * tid + w][1]);
            cyn = fminf(cyn, wred[4 * tid + w][2]);
            cym = fmaxf(cym, wred[4 * tid + w][3]);
        }
        g_ext[set][slab * 4 + tid] = make_float4(cxn, cxm, cyn, cym);
    }
}

// ---------- K3: diag (3 slabs, group-pruned) + worklist build ----------
__global__ void __launch_bounds__(CELL)
k_diagbuild() {
    const int qc = blockIdx.x, p = blockIdx.y, tid = threadIdx.x;
    const int lane = tid & 31, w4 = tid >> 5;
    const int rset = 1 - p;
    __shared__ float4 sref[3 * SLAB];     // slabs qslab-1, qslab, qslab+1

    const int qp = qc * CELL + tid;
    const float4 q = g_pts[p][qp];
    const float nx = -q.x, ny = -q.y, nz = -q.z;
    const int qslab = qc >> 2;
    const float4* __restrict__ refs = g_pts[rset];

    // stage valid slabs
#pragma unroll
    for (int sd = -1; sd <= 1; sd++) {
        int rs = qslab + sd;
        if (rs < 0 || rs >= NSLAB) continue;
#pragma unroll
        for (int k = 0; k < SLAB / CELL; k++)
            sref[(sd + 1) * SLAB + tid + k * CELL] = refs[rs * SLAB + tid + k * CELL];
    }
    __syncthreads();

    const int qw = qc * 4 + w4;
    const float4 wq = g_wext[p][qw];
    const int rw0 = (qc & 3) * 4 + w4;    // this warp's y-rank in its slab
    const int glo = max(rw0 - 1, 0), ghi = min(rw0 + 1, 15);

    // seed from y-aligned groups of own slab
    float m = __int_as_float(0x7f800000);
    for (int g = glo; g <= ghi; g++)
        m = eval32(&sref[SLAB + g * 32], nx, ny, nz, m);

    // remaining groups with running-cmax box tests (warp-uniform branches)
#pragma unroll
    for (int sd = -1; sd <= 1; sd++) {
        int rs = qslab + sd;
        if (rs < 0 || rs >= NSLAB) continue;
        for (int g = 0; g < 16; g++) {
            if (sd == 0 && g >= glo && g <= ghi) continue;
            float d2 = warpmax(2.0f * (m + q.w));
            float4 er = g_wext[rset][rs * 16 + g];
            float gx = fmaxf(fmaxf(er.x - wq.y, wq.x - er.y), 0.0f);
            float gy = fmaxf(fmaxf(er.z - wq.w, wq.z - er.w), 0.0f);
            if (gx * gx + gy * gy < d2)
                m = eval32(&sref[(sd + 1) * SLAB + g * 32], nx, ny, nz, m);
        }
    }
    g_minbits[p][qp] = fflip(m);          // exclusive owner

    // build off-diagonal worklist (per-warp cmax vs ref-cell boxes)
    float d2 = warpmax(fmaxf(2.0f * (m + q.w), 0.0f));
#pragma unroll
    for (int k = 0; k < 4; k++) {
        int rc = lane + 32 * k;
        int rs = rc >> 2;
        if (rs >= qslab - 1 && rs <= qslab + 1) continue;
        float4 er = g_ext[rset][rc];
        float gx = fmaxf(fmaxf(er.x - wq.y, wq.x - er.y), 0.0f);
        float gy = fmaxf(fmaxf(er.z - wq.w, wq.z - er.w), 0.0f);
        if (gx * gx + gy * gy < d2) {
            int w = atomicAdd(&g_nwork, 1);
            g_work[w] = (p << 16) | (qw << 7) | rc;
        }
    }
}

// ---------- K4: warp-per-item off-diag eval (group-pruned) + fused reduce ----------
__global__ void __launch_bounds__(256)
k_off(float* __restrict__ out) {
    __shared__ float4 sref[8][CELL];
    __shared__ float rsh[256];
    __shared__ int slast;
    const int wid = threadIdx.x >> 5, lane = threadIdx.x & 31;
    const int gw = blockIdx.x * 8 + wid;
    const int n = g_nwork;
    const float INF = __int_as_float(0x7f800000);

    for (int w = gw; w < n; w += OFFB * 8) {
        const int e = g_work[w];                 // warp-uniform
        const int rc = e & 127;
        const int qw = (e >> 7) & 511;
        const int p = e >> 16;

        const int qp = qw * 32 + lane;
        const float4 q = g_pts[p][qp];
        const float nx = -q.x, ny = -q.y, nz = -q.z;
        const float4 wq = g_wext[p][qw];

        // seed from current global min (sound pruning bound, value-deterministic)
        float m = funflip(g_minbits[p][qp]);
        float d2 = warpmax(2.0f * (m + q.w));

        // test the 4 ref-warp sub-boxes
        int live = 0;
        float gl2[4];
#pragma unroll
        for (int g = 0; g < 4; g++) {
            float4 er = g_wext[1 - p][rc * 4 + g];
            float gx = fmaxf(fmaxf(er.x - wq.y, wq.x - er.y), 0.0f);
            float gy = fmaxf(fmaxf(er.z - wq.w, wq.z - er.w), 0.0f);
            gl2[g] = gx * gx + gy * gy;
            live |= (gl2[g] < d2) << g;
        }
        if (!live) continue;

        __syncwarp();
#pragma unroll
        for (int k = 0; k < 4; k++)
            sref[wid][lane + 32 * k] = g_pts[1 - p][rc * CELL + lane + 32 * k];
        __syncwarp();

        float m0 = m;
#pragma unroll
        for (int g = 0; g < 4; g++) {
            if (gl2[g] < d2) {
                m0 = eval32(&sref[wid][g * 32], nx, ny, nz, m0);
                d2 = warpmax(2.0f * (m0 + q.w));
            }
        }
        if (m0 < m)
            atomicMin(&g_minbits[p][qp], fflip(m0));
    }

    // ----- fused reduction: last block to finish sums everything -----
    __threadfence();
    if (threadIdx.x == 0) slast = atomicAdd(&g_done, 1);
    __syncthreads();
    if (slast == OFFB - 1) {
        __threadfence();
        const u32* mb = (const u32*)g_minbits;
        const float4* pts = (const float4*)g_pts;
        float s = 0.0f;
        for (int i = threadIdx.x; i < 2 * NPTS; i += 256) {
            float mval = funflip(mb[i]);
            s += fmaxf(2.0f * (mval + pts[i].w), 0.0f);
        }
        rsh[threadIdx.x] = s;
        __syncthreads();
#pragma unroll
        for (int o = 128; o > 0; o >>= 1) {
            if (threadIdx.x < o) rsh[threadIdx.x] += rsh[threadIdx.x + o];
            __syncthreads();
        }
        if (threadIdx.x == 0)
            out[0] = rsh[0] * (1.0f / (float)NPTS);
    }
    (void)INF;
}

extern "C" void kernel_launch(void* const* d_in, const int* in_sizes, int n_in,
                              void* d_out, int out_size) {
    const float* pr = (const float*)d_in[0];   // predict [1,16384,3]
    const float* tg = (const float*)d_in[1];   // target  [1,16384,3]
    float* out = (float*)d_out;

    k_prep<<<2, PREPT>>>(pr, tg);

    dim3 ygrid(NSLAB, 2);
    k_ysort<<<ygrid, SLAB>>>();

    dim3 dgrid(NCELL, 2);
    k_diagbuild<<<dgrid, CELL>>>();

    k_off<<<OFFB, 256>>>(out);
}

// round 16
// speedup vs baseline: 1.0508x; 1.0508x over previous
#include <cuda_runtime.h>

#define NPTS   16384
#define NB     1024
#define YB     64
#define XMIN   (-5.0f)
#define INVW   ((float)NB / 10.0f)
#define SLAB   512
#define NSLAB  (NPTS / SLAB)              // 32
#define CELL   128
#define NCELL  (NPTS / CELL)              // 128
#define NQW    (NPTS / 32)                // 512 warps per set
#define PREPT  1024
#define OFFB   1024                       // k_off blocks (8 warps each)
#define MAXWORK (2 * NQW * NCELL)

typedef unsigned int u32;

// set 0 = predict, set 1 = target; pass p: queries = set p, refs = set 1-p
__device__ float4 g_pts[2][NPTS];         // x-slab then y-sorted (x,y,z, 0.5|p|^2)
__device__ u32    g_minbits[2][NPTS];     // flipped min-e
__device__ float4 g_ext[2][NCELL];        // per ref-cell box (xmin,xmax,ymin,ymax)
__device__ float4 g_wext[2][NQW];         // per warp box
__device__ int    g_nwork;
__device__ int    g_done;
__device__ int    g_work[MAXWORK];        // p<<16 | qw<<7 | rc

__device__ __forceinline__ int bin_of(float x) {
    int b = (int)((x - XMIN) * INVW);
    return min(max(b, 0), NB - 1);
}
__device__ __forceinline__ u32 fflip(float f) {
    u32 u = __float_as_uint(f);
    return (u & 0x80000000u) ? ~u : (u | 0x80000000u);
}
__device__ __forceinline__ float funflip(u32 u) {
    u = (u & 0x80000000u) ? (u ^ 0x80000000u) : ~u;
    return __uint_as_float(u);
}
__device__ __forceinline__ float warpmax(float v) {
#pragma unroll
    for (int o = 16; o > 0; o >>= 1)
        v = fmaxf(v, __shfl_xor_sync(0xFFFFFFFFu, v, o));
    return v;
}
// dense eval of 32 refs (shared), returns running min-e
__device__ __forceinline__ float eval32(const float4* r, float nx, float ny,
                                        float nz, float m) {
    float m0 = m, m1 = __int_as_float(0x7f800000);
#pragma unroll
    for (int j = 0; j < 32; j += 2) {
        float4 t0 = r[j], t1 = r[j + 1];
        float e;
        e = __fmaf_rn(nx, t0.x, t0.w); e = __fmaf_rn(ny, t0.y, e); e = __fmaf_rn(nz, t0.z, e);
        m0 = fminf(m0, e);
        e = __fmaf_rn(nx, t1.x, t1.w); e = __fmaf_rn(ny, t1.y, e); e = __fmaf_rn(nz, t1.z, e);
        m1 = fminf(m1, e);
    }
    return fminf(m0, m1);
}

// ---------- K1: x-bin sort, warp-shuffle scan (validated R15) ----------
__global__ void __launch_bounds__(PREPT)
k_prep(const float* __restrict__ pr, const float* __restrict__ tg) {
    __shared__ int sh[NB];
    __shared__ int wsum[32];
    const int s = blockIdx.x;
    const int tid = threadIdx.x;
    const int lane = tid & 31, w = tid >> 5;
    const float* __restrict__ src = s ? tg : pr;

    if (s == 0 && tid == 0) { g_nwork = 0; g_done = 0; }

    sh[tid] = 0;
    __syncthreads();
#pragma unroll
    for (int k = 0; k < NPTS / PREPT; k++) {
        int i = tid + k * PREPT;
        atomicAdd(&sh[bin_of(src[3 * i])], 1);
    }
    __syncthreads();

    int c = sh[tid];
    int v = c;
#pragma unroll
    for (int o = 1; o < 32; o <<= 1) {
        int n = __shfl_up_sync(0xFFFFFFFFu, v, o);
        if (lane >= o) v += n;
    }
    if (lane == 31) wsum[w] = v;
    __syncthreads();
    if (w == 0) {
        int t = wsum[lane];
#pragma unroll
        for (int o = 1; o < 32; o <<= 1) {
            int n = __shfl_up_sync(0xFFFFFFFFu, t, o);
            if (lane >= o) t += n;
        }
        wsum[lane] = t;
    }
    __syncthreads();
    int base = (w > 0) ? wsum[w - 1] : 0;
    sh[tid] = base + v - c;                 // exclusive offset = scatter cursor
    __syncthreads();

#pragma unroll
    for (int k = 0; k < NPTS / PREPT; k++) {
        int i = tid + k * PREPT;
        float x = src[3 * i], y = src[3 * i + 1], z = src[3 * i + 2];
        int pos = atomicAdd(&sh[bin_of(x)], 1);
        g_pts[s][pos] = make_float4(x, y, z, 0.5f * (x * x + y * y + z * z));
    }
}

// ---------- K2: y-sort each slab + per-warp boxes + per-cell boxes ----------
__global__ void __launch_bounds__(SLAB)
k_ysort() {
    __shared__ float4 buf[SLAB];
    __shared__ int hist[YB];
    __shared__ int cur[YB];
    __shared__ float wred[16][4];
    const int slab = blockIdx.x, set = blockIdx.y, tid = threadIdx.x;
    const int base = slab * SLAB;
    const int lane = tid & 31, wid = tid >> 5;

    float4 pt = g_pts[set][base + tid];
    if (tid < YB) hist[tid] = 0;
    __syncthreads();
    int yb = min(max((int)((pt.y - XMIN) * ((float)YB / 10.0f)), 0), YB - 1);
    atomicAdd(&hist[yb], 1);
    __syncthreads();
    if (tid == 0) {
        int acc = 0;
        for (int b = 0; b < YB; b++) { int v = hist[b]; cur[b] = acc; acc += v; }
    }
    __syncthreads();
    int pos = atomicAdd(&cur[yb], 1);
    buf[pos] = pt;
    __syncthreads();
    float4 sp = buf[tid];
    g_pts[set][base + tid] = sp;

    float xn = sp.x, xm = sp.x, yn = sp.y, ym = sp.y;
#pragma unroll
    for (int o = 16; o > 0; o >>= 1) {
        xn = fminf(xn, __shfl_xor_sync(0xFFFFFFFFu, xn, o));
        xm = fmaxf(xm, __shfl_xor_sync(0xFFFFFFFFu, xm, o));
        yn = fminf(yn, __shfl_xor_sync(0xFFFFFFFFu, yn, o));
        ym = fmaxf(ym, __shfl_xor_sync(0xFFFFFFFFu, ym, o));
    }
    if (lane == 0) {
        g_wext[set][slab * 16 + wid] = make_float4(xn, xm, yn, ym);
        wred[wid][0] = xn; wred[wid][1] = xm; wred[wid][2] = yn; wred[wid][3] = ym;
    }
    __syncthreads();
    if (tid < 4) {
        float cxn = wred[4 * tid][0], cxm = wred[4 * tid][1];
        float cyn = wred[4 * tid][2], cym = wred[4 * tid][3];
#pragma unroll
        for (int w = 1; w < 4; w++) {
            cxn = fminf(cxn, wred[4 * tid + w][0]);
            cxm = fmaxf(cxm, wred[4 * tid + w][1]);
            cyn = fminf(cyn, wred[4 * tid + w][2]);
            cym = fmaxf(cym, wred[4 * tid + w][3]);
        }
        g_ext[set][slab * 4 + tid] = make_float4(cxn, cxm, cyn, cym);
    }
}

// ---------- K3: diag (3 slabs, group-pruned) + worklist build (R15) ----------
__global__ void __launch_bounds__(CELL)
k_diagbuild() {
    const int qc = blockIdx.x, p = blockIdx.y, tid = threadIdx.x;
    const int lane = tid & 31, w4 = tid >> 5;
    const int rset = 1 - p;
    __shared__ float4 sref[3 * SLAB];     // slabs qslab-1, qslab, qslab+1

    const int qp = qc * CELL + tid;
    const float4 q = g_pts[p][qp];
    const float nx = -q.x, ny = -q.y, nz = -q.z;
    const int qslab = qc >> 2;
    const float4* __restrict__ refs = g_pts[rset];

#pragma unroll
    for (int sd = -1; sd <= 1; sd++) {
        int rs = qslab + sd;
        if (rs < 0 || rs >= NSLAB) continue;
#pragma unroll
        for (int k = 0; k < SLAB / CELL; k++)
            sref[(sd + 1) * SLAB + tid + k * CELL] = refs[rs * SLAB + tid + k * CELL];
    }
    __syncthreads();

    const int qw = qc * 4 + w4;
    const float4 wq = g_wext[p][qw];
    const int rw0 = (qc & 3) * 4 + w4;    // this warp's y-rank in its slab
    const int glo = max(rw0 - 1, 0), ghi = min(rw0 + 1, 15);

    // seed from y-aligned groups of own slab
    float m = __int_as_float(0x7f800000);
    for (int g = glo; g <= ghi; g++)
        m = eval32(&sref[SLAB + g * 32], nx, ny, nz, m);

    // remaining groups with running-cmax box tests (warp-uniform branches)
#pragma unroll
    for (int sd = -1; sd <= 1; sd++) {
        int rs = qslab + sd;
        if (rs < 0 || rs >= NSLAB) continue;
        for (int g = 0; g < 16; g++) {
            if (sd == 0 && g >= glo && g <= ghi) continue;
            float d2 = warpmax(2.0f * (m + q.w));
            float4 er = g_wext[rset][rs * 16 + g];
            float gx = fmaxf(fmaxf(er.x - wq.y, wq.x - er.y), 0.0f);
            float gy = fmaxf(fmaxf(er.z - wq.w, wq.z - er.w), 0.0f);
            if (gx * gx + gy * gy < d2)
                m = eval32(&sref[(sd + 1) * SLAB + g * 32], nx, ny, nz, m);
        }
    }
    g_minbits[p][qp] = fflip(m);          // exclusive owner

    // build off-diagonal worklist (per-warp cmax vs ref-cell boxes)
    float d2 = warpmax(fmaxf(2.0f * (m + q.w), 0.0f));
#pragma unroll
    for (int k = 0; k < 4; k++) {
        int rc = lane + 32 * k;
        int rs = rc >> 2;
        if (rs >= qslab - 1 && rs <= qslab + 1) continue;
        float4 er = g_ext[rset][rc];
        float gx = fmaxf(fmaxf(er.x - wq.y, wq.x - er.y), 0.0f);
        float gy = fmaxf(fmaxf(er.z - wq.w, wq.z - er.w), 0.0f);
        if (gx * gx + gy * gy < d2) {
            int w = atomicAdd(&g_nwork, 1);
            g_work[w] = (p << 16) | (qw << 7) | rc;
        }
    }
}

// ---------- K4: lean warp-per-item off-diag eval (R14 body) + fused reduce ----------
__global__ void __launch_bounds__(256)
k_off(float* __restrict__ out) {
    __shared__ float4 sref[8][CELL];
    __shared__ float rsh[256];
    __shared__ int slast;
    const int wid = threadIdx.x >> 5, lane = threadIdx.x & 31;
    const int gw = blockIdx.x * 8 + wid;
    const int n = g_nwork;
    const float INF = __int_as_float(0x7f800000);

    for (int w = gw; w < n; w += OFFB * 8) {
        const int e = g_work[w];                 // warp-uniform
        const int rc = e & 127;
        const int qw = (e >> 7) & 511;
        const int p = e >> 16;

        __syncwarp();
#pragma unroll
        for (int k = 0; k < 4; k++)
            sref[wid][lane + 32 * k] = g_pts[1 - p][rc * CELL + lane + 32 * k];
        __syncwarp();

        const int qp = qw * 32 + lane;
        const float4 q = g_pts[p][qp];
        const float nx = -q.x, ny = -q.y, nz = -q.z;

        float m0 = INF, m1 = INF;
#pragma unroll 4
        for (int j = 0; j < CELL; j += 2) {
            float4 t0 = sref[wid][j];
            float4 t1 = sref[wid][j + 1];
            float ev;
            ev = __fmaf_rn(nx, t0.x, t0.w); ev = __fmaf_rn(ny, t0.y, ev); ev = __fmaf_rn(nz, t0.z, ev);
            m0 = fminf(m0, ev);
            ev = __fmaf_rn(nx, t1.x, t1.w); ev = __fmaf_rn(ny, t1.y, ev); ev = __fmaf_rn(nz, t1.z, ev);
            m1 = fminf(m1, ev);
        }
        atomicMin(&g_minbits[p][qp], fflip(fminf(m0, m1)));
    }

    // ----- fused reduction: last block to finish sums everything -----
    __threadfence();
    if (threadIdx.x == 0) slast = atomicAdd(&g_done, 1);
    __syncthreads();
    if (slast == OFFB - 1) {
        __threadfence();
        const u32* mb = (const u32*)g_minbits;
        const float4* pts = (const float4*)g_pts;
        float s = 0.0f;
        for (int i = threadIdx.x; i < 2 * NPTS; i += 256) {
            float mval = funflip(mb[i]);
            s += fmaxf(2.0f * (mval + pts[i].w), 0.0f);
        }
        rsh[threadIdx.x] = s;
        __syncthreads();
#pragma unroll
        for (int o = 128; o > 0; o >>= 1) {
            if (threadIdx.x < o) rsh[threadIdx.x] += rsh[threadIdx.x + o];
            __syncthreads();
        }
        if (threadIdx.x == 0)
            out[0] = rsh[0] * (1.0f / (float)NPTS);
    }
}

extern "C" void kernel_launch(void* const* d_in, const int* in_sizes, int n_in,
                              void* d_out, int out_size) {
    const float* pr = (const float*)d_in[0];   // predict [1,16384,3]
    const float* tg = (const float*)d_in[1];   // target  [1,16384,3]
    float* out = (float*)d_out;

    k_prep<<<2, PREPT>>>(pr, tg);

    dim3 ygrid(NSLAB, 2);
    k_ysort<<<ygrid, SLAB>>>();

    dim3 dgrid(NCELL, 2);
    k_diagbuild<<<dgrid, CELL>>>();

    k_off<<<OFFB, 256>>>(out);
}

// round 17
// speedup vs baseline: 1.0952x; 1.0423x over previous
#include <cuda_runtime.h>

#define NPTS   16384
#define NB     1024
#define YB     64
#define XMIN   (-5.0f)
#define INVW   ((float)NB / 10.0f)
#define SLAB   512
#define NSLAB  (NPTS / SLAB)              // 32
#define CELL   128
#define NCELL  (NPTS / CELL)              // 128
#define NQW    (NPTS / 32)                // 512 query warps per set
#define PREPT  1024
#define OFFB   1024                       // k_off blocks (8 warps each)
#define MAXWORK (2 * NQW * NCELL)

typedef unsigned int u32;

// set 0 = predict, set 1 = target; pass p: queries = set p, refs = set 1-p
__device__ float4 g_pts[2][NPTS];         // x-slab then y-sorted (x,y,z, 0.5|p|^2)
__device__ u32    g_minbits[2][NPTS];     // flipped min-e
__device__ float4 g_ext[2][NCELL];        // per ref-cell box (xmin,xmax,ymin,ymax)
__device__ float4 g_wext[2][NQW];         // per query-warp box
__device__ int    g_nwork;
__device__ int    g_work[MAXWORK];        // p<<16 | qw<<7 | rc

__device__ __forceinline__ int bin_of(float x) {
    int b = (int)((x - XMIN) * INVW);
    return min(max(b, 0), NB - 1);
}
__device__ __forceinline__ u32 fflip(float f) {
    u32 u = __float_as_uint(f);
    return (u & 0x80000000u) ? ~u : (u | 0x80000000u);
}
__device__ __forceinline__ float funflip(u32 u) {
    u = (u & 0x80000000u) ? (u ^ 0x80000000u) : ~u;
    return __uint_as_float(u);
}

// ---------- K1: x-bin sort with warp-shuffle scan (validated R15/R16) ----------
__global__ void __launch_bounds__(PREPT)
k_prep(const float* __restrict__ pr, const float* __restrict__ tg) {
    __shared__ int sh[NB];
    __shared__ int wsum[32];
    const int s = blockIdx.x;
    const int tid = threadIdx.x;
    const int lane = tid & 31, w = tid >> 5;
    const float* __restrict__ src = s ? tg : pr;

    if (s == 0 && tid == 0) g_nwork = 0;

    sh[tid] = 0;
    __syncthreads();
#pragma unroll
    for (int k = 0; k < NPTS / PREPT; k++) {
        int i = tid + k * PREPT;
        atomicAdd(&sh[bin_of(src[3 * i])], 1);
    }
    __syncthreads();

    // warp-shuffle inclusive scan over NB bins (2 barriers)
    int c = sh[tid];
    int v = c;
#pragma unroll
    for (int o = 1; o < 32; o <<= 1) {
        int n = __shfl_up_sync(0xFFFFFFFFu, v, o);
        if (lane >= o) v += n;
    }
    if (lane == 31) wsum[w] = v;
    __syncthreads();
    if (w == 0) {
        int t = wsum[lane];
#pragma unroll
        for (int o = 1; o < 32; o <<= 1) {
            int n = __shfl_up_sync(0xFFFFFFFFu, t, o);
            if (lane >= o) t += n;
        }
        wsum[lane] = t;
    }
    __syncthreads();
    int base = (w > 0) ? wsum[w - 1] : 0;
    sh[tid] = base + v - c;                 // exclusive offset = scatter cursor
    __syncthreads();

#pragma unroll
    for (int k = 0; k < NPTS / PREPT; k++) {
        int i = tid + k * PREPT;
        float x = src[3 * i], y = src[3 * i + 1], z = src[3 * i + 2];
        int pos = atomicAdd(&sh[bin_of(x)], 1);
        g_pts[s][pos] = make_float4(x, y, z, 0.5f * (x * x + y * y + z * z));
    }
}

// ---------- K2: y-sort each slab + per-warp boxes + per-cell boxes (R14) ----------
__global__ void __launch_bounds__(SLAB)
k_ysort() {
    __shared__ float4 buf[SLAB];
    __shared__ int hist[YB];
    __shared__ int cur[YB];
    __shared__ float wred[16][4];
    const int slab = blockIdx.x, set = blockIdx.y, tid = threadIdx.x;
    const int base = slab * SLAB;
    const int lane = tid & 31, wid = tid >> 5;

    float4 pt = g_pts[set][base + tid];
    if (tid < YB) hist[tid] = 0;
    __syncthreads();
    int yb = min(max((int)((pt.y - XMIN) * ((float)YB / 10.0f)), 0), YB - 1);
    atomicAdd(&hist[yb], 1);
    __syncthreads();
    if (tid == 0) {
        int acc = 0;
        for (int b = 0; b < YB; b++) { int v = hist[b]; cur[b] = acc; acc += v; }
    }
    __syncthreads();
    int pos = atomicAdd(&cur[yb], 1);
    buf[pos] = pt;
    __syncthreads();
    float4 sp = buf[tid];
    g_pts[set][base + tid] = sp;

    float xn = sp.x, xm = sp.x, yn = sp.y, ym = sp.y;
#pragma unroll
    for (int o = 16; o > 0; o >>= 1) {
        xn = fminf(xn, __shfl_xor_sync(0xFFFFFFFFu, xn, o));
        xm = fmaxf(xm, __shfl_xor_sync(0xFFFFFFFFu, xm, o));
        yn = fminf(yn, __shfl_xor_sync(0xFFFFFFFFu, yn, o));
        ym = fmaxf(ym, __shfl_xor_sync(0xFFFFFFFFu, ym, o));
    }
    if (lane == 0) {
        g_wext[set][slab * 16 + wid] = make_float4(xn, xm, yn, ym);
        wred[wid][0] = xn; wred[wid][1] = xm; wred[wid][2] = yn; wred[wid][3] = ym;
    }
    __syncthreads();
    if (tid < 4) {
        float cxn = wred[4 * tid][0], cxm = wred[4 * tid][1];
        float cyn = wred[4 * tid][2], cym = wred[4 * tid][3];
#pragma unroll
        for (int w = 1; w < 4; w++) {
            cxn = fminf(cxn, wred[4 * tid + w][0]);
            cxm = fmaxf(cxm, wred[4 * tid + w][1]);
            cyn = fminf(cyn, wred[4 * tid + w][2]);
            cym = fmaxf(cym, wred[4 * tid + w][3]);
        }
        g_ext[set][slab * 4 + tid] = make_float4(cxn, cxm, cyn, cym);
    }
}

// ---------- K3: fused diag (3 slabs, one at a time) + build (R14 verbatim) ----------
__global__ void __launch_bounds__(CELL)
k_diagbuild() {
    const int qc = blockIdx.x, p = blockIdx.y, tid = threadIdx.x;
    const int lane = tid & 31, w4 = tid >> 5;
    __shared__ float4 sref[SLAB];

    const int qp = qc * CELL + tid;
    const float4 q = g_pts[p][qp];
    const float nx = -q.x, ny = -q.y, nz = -q.z;
    const int qslab = qc >> 2;
    const float4* __restrict__ refs = g_pts[1 - p];

    const float INF = __int_as_float(0x7f800000);
    float m0 = INF, m1 = INF;

#pragma unroll
    for (int sd = -1; sd <= 1; sd++) {
        int rs = qslab + sd;
        if (rs < 0 || rs >= NSLAB) continue;   // block-uniform
        __syncthreads();
#pragma unroll
        for (int k = 0; k < SLAB / CELL; k++)
            sref[tid + k * CELL] = refs[rs * SLAB + tid + k * CELL];
        __syncthreads();
#pragma unroll 4
        for (int j = 0; j < SLAB; j += 2) {
            float4 t0 = sref[j];
            float4 t1 = sref[j + 1];
            float e;
            e = __fmaf_rn(nx, t0.x, t0.w); e = __fmaf_rn(ny, t0.y, e); e = __fmaf_rn(nz, t0.z, e);
            m0 = fminf(m0, e);
            e = __fmaf_rn(nx, t1.x, t1.w); e = __fmaf_rn(ny, t1.y, e); e = __fmaf_rn(nz, t1.z, e);
            m1 = fminf(m1, e);
        }
    }
    float m = fminf(m0, m1);
    g_minbits[p][qp] = fflip(m);               // exclusive owner: plain store

    // ---- inline build: per-warp cmax + box tests ----
    float d2 = fmaxf(2.0f * (m + q.w), 0.0f);
#pragma unroll
    for (int o = 16; o > 0; o >>= 1)
        d2 = fmaxf(d2, __shfl_xor_sync(0xFFFFFFFFu, d2, o));   // warp cmax

    const int qw = qc * 4 + w4;
    const float4 wq = g_wext[p][qw];

#pragma unroll
    for (int k = 0; k < 4; k++) {
        int rc = lane + 32 * k;
        int rs = rc >> 2;
        if (rs >= qslab - 1 && rs <= qslab + 1) continue;   // diag-covered
        float4 er = g_ext[1 - p][rc];
        float gx = fmaxf(fmaxf(er.x - wq.y, wq.x - er.y), 0.0f);
        float gy = fmaxf(fmaxf(er.z - wq.w, wq.z - er.w), 0.0f);
        if (gx * gx + gy * gy < d2) {
            int w = atomicAdd(&g_nwork, 1);
            g_work[w] = (p << 16) | (qw << 7) | rc;
        }
    }
}

// ---------- K4: flat warp-per-item off-diagonal eval (R14 verbatim) ----------
__global__ void __launch_bounds__(256)
k_off() {
    __shared__ float4 sref[8][CELL];
    const int wid = threadIdx.x >> 5, lane = threadIdx.x & 31;
    const int gw = blockIdx.x * 8 + wid;
    const int n = g_nwork;
    const float INF = __int_as_float(0x7f800000);

    for (int w = gw; w < n; w += OFFB * 8) {
        const int e = g_work[w];                 // warp-uniform
        const int rc = e & 127;
        const int qw = (e >> 7) & 511;
        const int p = e >> 16;

        __syncwarp();
#pragma unroll
        for (int k = 0; k < 4; k++)
            sref[wid][lane + 32 * k] = g_pts[1 - p][rc * CELL + lane + 32 * k];
        __syncwarp();

        const int qp = qw * 32 + lane;
        const float4 q = g_pts[p][qp];
        const float nx = -q.x, ny = -q.y, nz = -q.z;

        float m0 = INF, m1 = INF;
#pragma unroll 4
        for (int j = 0; j < CELL; j += 2) {
            float4 t0 = sref[wid][j];
            float4 t1 = sref[wid][j + 1];
            float ev;
            ev = __fmaf_rn(nx, t0.x, t0.w); ev = __fmaf_rn(ny, t0.y, ev); ev = __fmaf_rn(nz, t0.z, ev);
            m0 = fminf(m0, ev);
            ev = __fmaf_rn(nx, t1.x, t1.w); ev = __fmaf_rn(ny, t1.y, ev); ev = __fmaf_rn(nz, t1.z, ev);
            m1 = fminf(m1, ev);
        }
        atomicMin(&g_minbits[p][qp], fflip(fminf(m0, m1)));
    }
}

// ---------- K5: deterministic reduction (R14 verbatim) ----------
__global__ void __launch_bounds__(1024)
k_reduce(float* __restrict__ out) {
    __shared__ float sh[1024];
    float sum = 0.0f;
#pragma unroll
    for (int p = 0; p < 2; p++) {
        for (int i = threadIdx.x; i < NPTS; i += 1024) {
            float4 q = g_pts[p][i];
            float m = funflip(g_minbits[p][i]);
            sum += fmaxf(2.0f * (m + q.w), 0.0f);
        }
    }
    sh[threadIdx.x] = sum;
    __syncthreads();
#pragma unroll
    for (int o = 512; o > 0; o >>= 1) {
        if (threadIdx.x < o) sh[threadIdx.x] += sh[threadIdx.x + o];
        __syncthreads();
    }
    if (threadIdx.x == 0)
        out[0] = sh[0] * (1.0f / (float)NPTS);
}

extern "C" void kernel_launch(void* const* d_in, const int* in_sizes, int n_in,
                              void* d_out, int out_size) {
    const float* pr = (const float*)d_in[0];   // predict [1,16384,3]
    const float* tg = (const float*)d_in[1];   // target  [1,16384,3]
    float* out = (float*)d_out;

    k_prep<<<2, PREPT>>>(pr, tg);

    dim3 ygrid(NSLAB, 2);
    k_ysort<<<ygrid, SLAB>>>();

    dim3 dgrid(NCELL, 2);
    k_diagbuild<<<dgrid, CELL>>>();

    k_off<<<OFFB, 256>>>();

    k_reduce<<<1, 1024>>>(out);
}